// round 7
// baseline (speedup 1.0000x reference)
#include <cuda_runtime.h>
#include <cuda_bf16.h>
#include <cuda_fp16.h>
#include <math.h>
#include <stdint.h>

// Problem constants (fixed by setup_inputs)
#define BB 512       // batch
#define TT 64        // text seq len
#define EE 50        // embedding dim
#define HH 32        // rnn hidden
#define NN 32768     // timeline sequences
#define TT2 32       // timeline seq len
#define FC_IN 305

// ---------------- scratch (no allocations allowed) ----------------
__device__ float g_h2[(size_t)NN * 64];    // [N, 64] timeline biRNN final hidden
__device__ float g_hn[(size_t)BB * 64];    // [B, 64] text biRNN final hidden

// ==================== helpers (plain sm_100-safe: sm_80+ features only) ====================
__device__ __forceinline__ uint32_t smem_u32(const void* p) {
    uint32_t a;
    asm("{ .reg .u64 t; cvta.to.shared.u64 t, %1; cvt.u32.u64 %0, t; }" : "=r"(a) : "l"(p));
    return a;
}
__device__ __forceinline__ uint32_t pack_h2(float a, float b) {
    __half2 h = __floats2half2_rn(a, b);
    return *(uint32_t*)&h;
}
// ld.shared.v2.f32 + convert to packed half2
__device__ __forceinline__ uint32_t lds2h(uint32_t addr) {
    float x, y;
    asm volatile("ld.shared.v2.f32 {%0,%1}, [%2];" : "=f"(x), "=f"(y) : "r"(addr));
    return pack_h2(x, y);
}
__device__ __forceinline__ void sts_f(uint32_t a, float v) {
    asm volatile("st.shared.f32 [%0], %1;" :: "r"(a), "f"(v));
}
__device__ __forceinline__ void sts_v2(uint32_t a, float x, float y) {
    asm volatile("st.shared.v2.f32 [%0], {%1, %2};" :: "r"(a), "f"(x), "f"(y));
}
__device__ __forceinline__ void cp_async8(uint32_t saddr, const void* gaddr) {
    asm volatile("cp.async.ca.shared.global [%0], [%1], 8;" :: "r"(saddr), "l"(gaddr));
}
#define CP_COMMIT() asm volatile("cp.async.commit_group;" ::: "memory")
#define CP_WAIT0()  asm volatile("cp.async.wait_group 0;" ::: "memory")

// D += A*B : m16n8k16 fp16 in, fp32 accum (A row-major, B col-major)
__device__ __forceinline__ void mma16(float c[4], const uint32_t a[4], const uint32_t b[2]) {
    asm volatile("mma.sync.aligned.m16n8k16.row.col.f32.f16.f16.f32 "
        "{%0,%1,%2,%3}, {%4,%5,%6,%7}, {%8,%9}, {%0,%1,%2,%3};"
        : "+f"(c[0]), "+f"(c[1]), "+f"(c[2]), "+f"(c[3])
        : "r"(a[0]), "r"(a[1]), "r"(a[2]), "r"(a[3]), "r"(b[0]), "r"(b[1]));
}

__device__ __forceinline__ float ftanh(float x) {
    float cx = fminf(fmaxf(x, -15.f), 15.f);
    float e = __expf(2.f * cx);
    return (e - 1.f) * __frcp_rn(e + 1.f);
}

// ==================== per-warp SMEM layout (timeline branch) ====================
// xbuf: 16 rows x 72 floats (50 data, cols 50..63 zeroed, 64..71 unused pad), double-buffered
// hbuf: 16 rows x 36 floats (32 data + pad)
#define XW          72
#define XBUF_BYTES  (16 * XW * 4)                       // 4608
#define HBUF_BYTES  (16 * 36 * 4)                       // 2304
#define WARP_SMEM   (2 * XBUF_BYTES + HBUF_BYTES)       // 11520
// CTA: 4 warps -> 46080 bytes (< 48KB static limit)

// ==================== fused RNN kernel ====================
// blocks 0..1023:    timeline biRNN via mma.sync fp16-k16 (dir = b&1, 64 seqs per CTA)
// blocks 1024..1279: text biRNN via shuffle path (4 warps/block)
__global__ __launch_bounds__(128)
void fused_rnn(const float* __restrict__ tlx, const float* __restrict__ txx,
               const float* __restrict__ r2wif, const float* __restrict__ r2whf,
               const float* __restrict__ r2bif, const float* __restrict__ r2bhf,
               const float* __restrict__ r2wib, const float* __restrict__ r2whb,
               const float* __restrict__ r2bib, const float* __restrict__ r2bhb,
               const float* __restrict__ r1wif, const float* __restrict__ r1whf,
               const float* __restrict__ r1bif, const float* __restrict__ r1bhf,
               const float* __restrict__ r1wib, const float* __restrict__ r1whb,
               const float* __restrict__ r1bib, const float* __restrict__ r1bhb)
{
    __shared__ __align__(16) unsigned char s_raw[4 * WARP_SMEM];
    const int tid  = threadIdx.x;
    const int wid  = tid >> 5;
    const int lane = tid & 31;

    if (blockIdx.x < 1024) {
        // ---------------- timeline tensor-core path ----------------
        const int dir  = (int)(blockIdx.x & 1);
        const int tile = (int)(blockIdx.x >> 1);
        const int n0w  = tile * 64 + wid * 16;      // warp's first sequence

        const float* wih = dir ? r2wib : r2wif;
        const float* whh = dir ? r2whb : r2whf;
        const float* bi  = dir ? r2bib : r2bif;
        const float* bh  = dir ? r2bhb : r2bhf;

        const int g  = lane >> 2;    // 0..7
        const int t4 = lane & 3;     // 0..3

        const uint32_t wb  = smem_u32(s_raw) + (uint32_t)wid * WARP_SMEM;
        const uint32_t xb0 = wb;
        const uint32_t xb1 = wb + XBUF_BYTES;
        const uint32_t hb  = wb + 2 * XBUF_BYTES;

        // zero pad columns 50..63 of both x buffers (k-tile 3 reads cols 48..63)
        if (lane < 16) {
#pragma unroll
            for (int k = 0; k < 14; k++) {
                sts_f(xb0 + (uint32_t)(lane * XW + 50 + k) * 4u, 0.f);
                sts_f(xb1 + (uint32_t)(lane * XW + 50 + k) * 4u, 0.f);
            }
        }

        // ---- weight B-fragments (col-major B[k][n] = W[n][k]), fp16x2 in registers ----
        // h part: K=32 -> 2 k-tiles of 16
        uint32_t wbh[2][4][2];
#pragma unroll
        for (int kt = 0; kt < 2; kt++)
#pragma unroll
            for (int nt = 0; nt < 4; nt++) {
                int row = nt * 8 + g;
                int c0 = kt * 16 + t4 * 2;
                wbh[kt][nt][0] = pack_h2(whh[row * 32 + c0],     whh[row * 32 + c0 + 1]);
                wbh[kt][nt][1] = pack_h2(whh[row * 32 + c0 + 8], whh[row * 32 + c0 + 9]);
            }
        // x part: K=50 -> 4 k-tiles of 16 (padded to 64)
        uint32_t wbx[4][4][2];
#pragma unroll
        for (int kt = 0; kt < 4; kt++)
#pragma unroll
            for (int nt = 0; nt < 4; nt++) {
                int row = nt * 8 + g;
                int c0 = kt * 16 + t4 * 2;
                float v00 = (c0     < EE) ? wih[row * EE + c0]     : 0.f;
                float v01 = (c0 + 1 < EE) ? wih[row * EE + c0 + 1] : 0.f;
                float v10 = (c0 + 8 < EE) ? wih[row * EE + c0 + 8] : 0.f;
                float v11 = (c0 + 9 < EE) ? wih[row * EE + c0 + 9] : 0.f;
                wbx[kt][nt][0] = pack_h2(v00, v01);
                wbx[kt][nt][1] = pack_h2(v10, v11);
            }
        float bb[4][2];
#pragma unroll
        for (int nt = 0; nt < 4; nt++) {
            int col = nt * 8 + t4 * 2;
            bb[nt][0] = bi[col] + bh[col];
            bb[nt][1] = bi[col + 1] + bh[col + 1];
        }

        // ---- x staging plan: row = lane&15, half = lane>>4 ----
        const int xrow = lane & 15;
        const int half = lane >> 4;              // 0: cols 0..25 (13 x 8B); 1: cols 26..49 (12 x 8B)
        const float* grow = tlx + (size_t)(n0w + xrow) * (TT2 * EE) + half * 26;
        const uint32_t soff = (uint32_t)(xrow * XW + half * 26) * 4u;

        // stage t = 0 into buf0
        {
            int te0 = dir ? (TT2 - 1) : 0;
            const float* gp = grow + te0 * EE;
#pragma unroll
            for (int j = 0; j < 13; j++)
                if (half == 0 || j < 12)
                    cp_async8(xb0 + soff + 8u * j, gp + 2 * j);
            CP_COMMIT();
            CP_WAIT0();
            __syncwarp();
        }

        uint32_t ha[2][4];
#pragma unroll
        for (int kt = 0; kt < 2; kt++)
#pragma unroll
            for (int i = 0; i < 4; i++) ha[kt][i] = 0u;

        float accx[4][4], acch[4][4];

#pragma unroll 1
        for (int t = 0; t < TT2; t++) {
            // prefetch x(t+1) into alternate buffer
            if (t + 1 < TT2) {
                int te = dir ? (TT2 - 2 - t) : (t + 1);
                uint32_t dst = ((t + 1) & 1) ? xb1 : xb0;
                const float* gp = grow + te * EE;
#pragma unroll
                for (int j = 0; j < 13; j++)
                    if (half == 0 || j < 12)
                        cp_async8(dst + soff + 8u * j, gp + 2 * j);
                CP_COMMIT();
            }

            // init accumulators: x-chain from bias, h-chain from zero (8 indep chains)
#pragma unroll
            for (int nt = 0; nt < 4; nt++) {
                accx[nt][0] = bb[nt][0]; accx[nt][1] = bb[nt][1];
                accx[nt][2] = bb[nt][0]; accx[nt][3] = bb[nt][1];
                acch[nt][0] = 0.f; acch[nt][1] = 0.f; acch[nt][2] = 0.f; acch[nt][3] = 0.f;
            }
            // h contribution (critical path) — 2 k-tiles
#pragma unroll
            for (int kt = 0; kt < 2; kt++)
#pragma unroll
                for (int nt = 0; nt < 4; nt++)
                    mma16(acch[nt], ha[kt], wbh[kt][nt]);
            // x contribution — 4 k-tiles (independent of h; fills latency)
            const uint32_t cur = (t & 1) ? xb1 : xb0;
#pragma unroll
            for (int kt = 0; kt < 4; kt++) {
                uint32_t xa[4];
                uint32_t ba = cur + (uint32_t)(g * (XW * 4) + kt * 64 + t4 * 8);
                xa[0] = lds2h(ba);
                xa[1] = lds2h(ba + 8u * XW * 4u);
                xa[2] = lds2h(ba + 32u);
                xa[3] = lds2h(ba + 8u * XW * 4u + 32u);
#pragma unroll
                for (int nt = 0; nt < 4; nt++)
                    mma16(accx[nt], xa, wbx[kt][nt]);
            }
            // combine + tanh
            float v[4][4];
#pragma unroll
            for (int nt = 0; nt < 4; nt++)
#pragma unroll
                for (int i = 0; i < 4; i++)
                    v[nt][i] = ftanh(accx[nt][i] + acch[nt][i]);

            if (t == TT2 - 1) {
#pragma unroll
                for (int nt = 0; nt < 4; nt++) {
                    int col = dir * 32 + nt * 8 + t4 * 2;
                    *(float2*)(g_h2 + (size_t)(n0w + g) * 64 + col)     = make_float2(v[nt][0], v[nt][1]);
                    *(float2*)(g_h2 + (size_t)(n0w + g + 8) * 64 + col) = make_float2(v[nt][2], v[nt][3]);
                }
            } else {
                // write h to smem (f32, C layout), reload as fp16 A fragments
#pragma unroll
                for (int nt = 0; nt < 4; nt++) {
                    uint32_t a0 = hb + (uint32_t)(g * 36 + nt * 8 + t4 * 2) * 4u;
                    sts_v2(a0,         v[nt][0], v[nt][1]);
                    sts_v2(a0 + 1152u, v[nt][2], v[nt][3]);   // row g+8
                }
                CP_WAIT0();      // x prefetch landed
                __syncwarp();    // h visible warp-wide
#pragma unroll
                for (int kt = 0; kt < 2; kt++) {
                    uint32_t ba = hb + (uint32_t)(g * 144 + kt * 64 + t4 * 8);
                    ha[kt][0] = lds2h(ba);
                    ha[kt][1] = lds2h(ba + 1152u);
                    ha[kt][2] = lds2h(ba + 32u);
                    ha[kt][3] = lds2h(ba + 1184u);
                }
            }
        }
        return;
    }

    // ---------------- text shuffle path (blocks 1024..1279, 4 warps each) ----------------
    {
        float* s_wi = (float*)s_raw;                        // [2][HH*EE]
        float* s_wh = s_wi + 2 * HH * EE;                   // [2][HH*HH]
        float* s_b  = s_wh + 2 * HH * HH;                   // [2][HH]

        for (int k = tid; k < HH * EE; k += 128) { s_wi[k] = r1wif[k]; s_wi[HH * EE + k] = r1wib[k]; }
        for (int k = tid; k < HH * HH; k += 128) { s_wh[k] = r1whf[k]; s_wh[HH * HH + k] = r1whb[k]; }
        if (tid < HH) s_b[tid] = r1bif[tid] + r1bhf[tid];
        else if (tid < 2 * HH) { int j = tid - HH; s_b[HH + j] = r1bib[j] + r1bhb[j]; }
        __syncthreads();

        const int wglob = ((int)blockIdx.x - 1024) * 4 + wid;   // 0..1023
        const int dir = wglob & 1;
        const int seq = wglob >> 1;

        float wi[EE], wh[HH];
#pragma unroll
        for (int e = 0; e < EE; e++) wi[e] = s_wi[dir * HH * EE + lane * EE + e];
#pragma unroll
        for (int j = 0; j < HH; j++) wh[j] = s_wh[dir * HH * HH + lane * HH + j];
        const float biasv = s_b[dir * HH + lane];

        float h = 0.f;
        const float* xp = txx + (size_t)seq * TT * EE;

        const float* xt0 = xp + (size_t)(dir ? (TT - 1) : 0) * EE;
        float x1 = xt0[lane];
        float x2 = (lane < EE - 32) ? xt0[32 + lane] : 0.f;

#pragma unroll 1
        for (int t = 0; t < TT; t++) {
            float nx1 = 0.f, nx2 = 0.f;
            if (t + 1 < TT) {
                const float* xtn = xp + (size_t)(dir ? (TT - 2 - t) : (t + 1)) * EE;
                nx1 = xtn[lane];
                nx2 = (lane < EE - 32) ? xtn[32 + lane] : 0.f;
            }
            float a0 = biasv, a1 = 0.f, a2 = 0.f, a3 = 0.f;
#pragma unroll
            for (int e = 0; e < 32; e += 4) {
                a0 = fmaf(__shfl_sync(0xffffffffu, x1, e + 0), wi[e + 0], a0);
                a1 = fmaf(__shfl_sync(0xffffffffu, x1, e + 1), wi[e + 1], a1);
                a2 = fmaf(__shfl_sync(0xffffffffu, x1, e + 2), wi[e + 2], a2);
                a3 = fmaf(__shfl_sync(0xffffffffu, x1, e + 3), wi[e + 3], a3);
            }
#pragma unroll
            for (int e = 0; e < 16; e += 4) {
                a0 = fmaf(__shfl_sync(0xffffffffu, x2, e + 0), wi[32 + e + 0], a0);
                a1 = fmaf(__shfl_sync(0xffffffffu, x2, e + 1), wi[32 + e + 1], a1);
                a2 = fmaf(__shfl_sync(0xffffffffu, x2, e + 2), wi[32 + e + 2], a2);
                a3 = fmaf(__shfl_sync(0xffffffffu, x2, e + 3), wi[32 + e + 3], a3);
            }
            a0 = fmaf(__shfl_sync(0xffffffffu, x2, 16), wi[48], a0);
            a1 = fmaf(__shfl_sync(0xffffffffu, x2, 17), wi[49], a1);
#pragma unroll
            for (int j = 0; j < 32; j += 4) {
                a0 = fmaf(__shfl_sync(0xffffffffu, h, j + 0), wh[j + 0], a0);
                a1 = fmaf(__shfl_sync(0xffffffffu, h, j + 1), wh[j + 1], a1);
                a2 = fmaf(__shfl_sync(0xffffffffu, h, j + 2), wh[j + 2], a2);
                a3 = fmaf(__shfl_sync(0xffffffffu, h, j + 3), wh[j + 3], a3);
            }
            h = tanhf((a0 + a2) + (a1 + a3));
            x1 = nx1; x2 = nx2;
        }
        g_hn[(size_t)seq * 64 + dir * 32 + lane] = h;
    }
}

// ==================== fused segment stats + FC ====================
// block b (64 threads): ragged mean/min/max of g_h2 rows for segment b, then fc1+fc2.
// 4-way unrolled reduce for MLP (the R6 profile showed this kernel latency-bound at MLP=1).
__global__ void segfc_kernel(const int* __restrict__ counts,
                             const float* __restrict__ normal,
                             const float* __restrict__ fc1w, const float* __restrict__ fc1b,
                             const float* __restrict__ fc2w, const float* __restrict__ fc2b,
                             float* __restrict__ out)
{
    __shared__ float feat[FC_IN];
    __shared__ int wsum[2];
    const int b = blockIdx.x;
    const int c = threadIdx.x;   // 0..63

    int part = 0;
    for (int i = c; i < b; i += 64) part += counts[i];
#pragma unroll
    for (int o = 16; o > 0; o >>= 1) part += __shfl_xor_sync(0xffffffffu, part, o);
    if ((c & 31) == 0) wsum[c >> 5] = part;
    __syncthreads();
    const size_t start = (size_t)(wsum[0] + wsum[1]);
    const int cnt = counts[b];

    const float* p = g_h2 + start * 64 + c;
    float s0 = 0.f, s1 = 0.f, s2 = 0.f, s3 = 0.f;
    float mn0 = 2.f, mn1 = 2.f, mx0 = -2.f, mx1 = -2.f;
    int r = 0;
    for (; r + 4 <= cnt; r += 4) {
        float v0 = p[(size_t)(r + 0) * 64];
        float v1 = p[(size_t)(r + 1) * 64];
        float v2 = p[(size_t)(r + 2) * 64];
        float v3 = p[(size_t)(r + 3) * 64];
        s0 += v0; s1 += v1; s2 += v2; s3 += v3;
        mn0 = fminf(mn0, fminf(v0, v1)); mn1 = fminf(mn1, fminf(v2, v3));
        mx0 = fmaxf(mx0, fmaxf(v0, v1)); mx1 = fmaxf(mx1, fmaxf(v2, v3));
    }
    for (; r < cnt; r++) {
        float v = p[(size_t)r * 64];
        s0 += v; mn0 = fminf(mn0, v); mx0 = fmaxf(mx0, v);
    }
    float s = (s0 + s1) + (s2 + s3);
    float mn = fminf(mn0, mn1), mx = fmaxf(mx0, mx1);

    feat[c] = g_hn[(size_t)b * 64 + c];
    if (c < 49) feat[64 + c] = normal[(size_t)b * 49 + c];
    feat[113 + c] = s / (float)cnt;
    feat[177 + c] = mn;
    feat[241 + c] = mx;
    __syncthreads();

    if (c < 32) {
        float a0 = fc1b[c], a1 = 0.f, a2 = 0.f, a3 = 0.f;
        const float* w = fc1w + (size_t)c * FC_IN;
#pragma unroll 4
        for (int k = 0; k < 304; k += 4) {
            a0 = fmaf(feat[k + 0], w[k + 0], a0);
            a1 = fmaf(feat[k + 1], w[k + 1], a1);
            a2 = fmaf(feat[k + 2], w[k + 2], a2);
            a3 = fmaf(feat[k + 3], w[k + 3], a3);
        }
        a0 = fmaf(feat[304], w[304], a0);
        float tv = tanhf((a0 + a2) + (a1 + a3)) * fc2w[c];
#pragma unroll
        for (int o = 16; o > 0; o >>= 1) tv += __shfl_xor_sync(0xffffffffu, tv, o);
        if (c == 0) out[b] = 1.f / (1.f + expf(-(tv + fc2b[0])));
    }
}

// ==================== launch ====================
extern "C" void kernel_launch(void* const* d_in, const int* in_sizes, int n_in,
                              void* d_out, int out_size)
{
    const float* normal   = (const float*)d_in[0];
    const float* text     = (const float*)d_in[1];
    const float* timeline = (const float*)d_in[2];

    const int* telem;
    int base;
    if (in_sizes[3] == BB) { telem = (const int*)d_in[3];  base = 4; }
    else                   { telem = (const int*)d_in[23]; base = 3; }

    const float* r1[8];
    const float* r2[8];
    for (int k = 0; k < 8; k++) r1[k] = (const float*)d_in[base + k];
    for (int k = 0; k < 8; k++) r2[k] = (const float*)d_in[base + 8 + k];
    const float* fc1w = (const float*)d_in[base + 16];
    const float* fc1b = (const float*)d_in[base + 17];
    const float* fc2w = (const float*)d_in[base + 18];
    const float* fc2b = (const float*)d_in[base + 19];
    float* out = (float*)d_out;

    fused_rnn<<<1280, 128>>>(timeline, text,
        r2[0], r2[1], r2[2], r2[3], r2[4], r2[5], r2[6], r2[7],
        r1[0], r1[1], r1[2], r1[3], r1[4], r1[5], r1[6], r1[7]);

    segfc_kernel<<<BB, 64>>>(telem, normal, fc1w, fc1b, fc2w, fc2b, out);

    (void)n_in; (void)in_sizes; (void)out_size;
}

// round 9
// speedup vs baseline: 1.0804x; 1.0804x over previous
#include <cuda_runtime.h>
#include <cuda_bf16.h>
#include <cuda_fp16.h>
#include <math.h>
#include <stdint.h>

// Problem constants (fixed by setup_inputs)
#define BB 512       // batch
#define TT 64        // text seq len
#define EE 50        // embedding dim
#define HH 32        // rnn hidden
#define NN 32768     // timeline sequences
#define TT2 32       // timeline seq len
#define FC_IN 305

// ---------------- scratch (no allocations allowed) ----------------
__device__ float g_h2[(size_t)NN * 64];    // [N, 64] timeline biRNN final hidden
__device__ float g_hn[(size_t)BB * 64];    // [B, 64] text biRNN final hidden

// ==================== helpers (plain sm_100-safe: sm_80+ features only) ====================
__device__ __forceinline__ uint32_t smem_u32(const void* p) {
    uint32_t a;
    asm("{ .reg .u64 t; cvta.to.shared.u64 t, %1; cvt.u32.u64 %0, t; }" : "=r"(a) : "l"(p));
    return a;
}
__device__ __forceinline__ uint32_t pack_h2(float a, float b) {
    __half2 h = __floats2half2_rn(a, b);
    return *(uint32_t*)&h;
}
__device__ __forceinline__ uint32_t lds2h(uint32_t addr) {  // ld.shared.v2.f32 -> half2
    float x, y;
    asm volatile("ld.shared.v2.f32 {%0,%1}, [%2];" : "=f"(x), "=f"(y) : "r"(addr));
    return pack_h2(x, y);
}
__device__ __forceinline__ void sts_f(uint32_t a, float v) {
    asm volatile("st.shared.f32 [%0], %1;" :: "r"(a), "f"(v));
}
__device__ __forceinline__ void cp_async8(uint32_t saddr, const void* gaddr) {
    asm volatile("cp.async.ca.shared.global [%0], [%1], 8;" :: "r"(saddr), "l"(gaddr));
}
#define CP_COMMIT() asm volatile("cp.async.commit_group;" ::: "memory")
#define CP_WAIT2()  asm volatile("cp.async.wait_group 2;" ::: "memory")

// D += A*B : m16n8k16 fp16 in, fp32 accum (A row-major, B col-major)
__device__ __forceinline__ void mma16(float c[4], const uint32_t a[4], const uint32_t b[2]) {
    asm volatile("mma.sync.aligned.m16n8k16.row.col.f32.f16.f16.f32 "
        "{%0,%1,%2,%3}, {%4,%5,%6,%7}, {%8,%9}, {%0,%1,%2,%3};"
        : "+f"(c[0]), "+f"(c[1]), "+f"(c[2]), "+f"(c[3])
        : "r"(a[0]), "r"(a[1]), "r"(a[2]), "r"(a[3]), "r"(b[0]), "r"(b[1]));
}

__device__ __forceinline__ float ftanh(float x) {
    float cx = fminf(fmaxf(x, -15.f), 15.f);
    float e = __expf(2.f * cx);
    return (e - 1.f) * __frcp_rn(e + 1.f);
}

// ==================== per-warp SMEM (timeline branch) ====================
// 4 x-buffers: 16 rows x 68 floats (50 data, 50..63 zeroed, 64..67 pad).
// Row stride 272B -> 68*g mod 32 banks = 4g: conflict-free LDS.64 fragments.
#define XW          68
#define XBUF_BYTES  (16 * XW * 4)        // 4352
#define WARP_SMEM   (4 * XBUF_BYTES)     // 17408
#define DYN_SMEM    (4 * WARP_SMEM)      // 69632 per CTA (needs opt-in)

// ==================== fused RNN kernel ====================
// blocks 0..1023:    timeline biRNN via mma.sync fp16-k16 (dir = b&1, 64 seqs per CTA)
// blocks 1024..1279: text biRNN via shuffle path (4 warps/block)
__global__ __launch_bounds__(128)
void fused_rnn(const float* __restrict__ tlx, const float* __restrict__ txx,
               const float* __restrict__ r2wif, const float* __restrict__ r2whf,
               const float* __restrict__ r2bif, const float* __restrict__ r2bhf,
               const float* __restrict__ r2wib, const float* __restrict__ r2whb,
               const float* __restrict__ r2bib, const float* __restrict__ r2bhb,
               const float* __restrict__ r1wif, const float* __restrict__ r1whf,
               const float* __restrict__ r1bif, const float* __restrict__ r1bhf,
               const float* __restrict__ r1wib, const float* __restrict__ r1whb,
               const float* __restrict__ r1bib, const float* __restrict__ r1bhb)
{
    extern __shared__ __align__(16) float dyn[];
    const int tid  = threadIdx.x;
    const int wid  = tid >> 5;
    const int lane = tid & 31;

    if (blockIdx.x < 1024) {
        // ---------------- timeline tensor-core path ----------------
        const int dir  = (int)(blockIdx.x & 1);
        const int tile = (int)(blockIdx.x >> 1);
        const int n0w  = tile * 64 + wid * 16;      // warp's first sequence

        const float* wih = dir ? r2wib : r2wif;
        const float* whh = dir ? r2whb : r2whf;
        const float* bi  = dir ? r2bib : r2bif;
        const float* bh  = dir ? r2bhb : r2bhf;

        const int g  = lane >> 2;    // 0..7
        const int t4 = lane & 3;     // 0..3

        const uint32_t wb = smem_u32(dyn) + (uint32_t)wid * WARP_SMEM;

        // zero pad columns 50..63 of all 4 buffers (k-tile 3 reads cols 48..63)
        if (lane < 16) {
#pragma unroll
            for (int bfi = 0; bfi < 4; bfi++)
#pragma unroll
                for (int k = 0; k < 14; k++)
                    sts_f(wb + (uint32_t)bfi * XBUF_BYTES + (uint32_t)(lane * XW + 50 + k) * 4u, 0.f);
        }

        // ---- weight B-fragments (col-major B[k][n] = W[n][k]), fp16x2 in registers ----
        uint32_t wbh[2][4][2];   // h: K=32, 2 k-tiles
#pragma unroll
        for (int kt = 0; kt < 2; kt++)
#pragma unroll
            for (int nt = 0; nt < 4; nt++) {
                int row = nt * 8 + g;
                int c0 = kt * 16 + t4 * 2;
                wbh[kt][nt][0] = pack_h2(whh[row * 32 + c0],     whh[row * 32 + c0 + 1]);
                wbh[kt][nt][1] = pack_h2(whh[row * 32 + c0 + 8], whh[row * 32 + c0 + 9]);
            }
        uint32_t wbx[4][4][2];   // x: K=50 padded to 64, 4 k-tiles
#pragma unroll
        for (int kt = 0; kt < 4; kt++)
#pragma unroll
            for (int nt = 0; nt < 4; nt++) {
                int row = nt * 8 + g;
                int c0 = kt * 16 + t4 * 2;
                float v00 = (c0     < EE) ? wih[row * EE + c0]     : 0.f;
                float v01 = (c0 + 1 < EE) ? wih[row * EE + c0 + 1] : 0.f;
                float v10 = (c0 + 8 < EE) ? wih[row * EE + c0 + 8] : 0.f;
                float v11 = (c0 + 9 < EE) ? wih[row * EE + c0 + 9] : 0.f;
                wbx[kt][nt][0] = pack_h2(v00, v01);
                wbx[kt][nt][1] = pack_h2(v10, v11);
            }
        float bb[4][2];
#pragma unroll
        for (int nt = 0; nt < 4; nt++) {
            int col = nt * 8 + t4 * 2;
            bb[nt][0] = bi[col] + bh[col];
            bb[nt][1] = bi[col + 1] + bh[col + 1];
        }

        // ---- x staging: row = lane&15, half = lane>>4 (cols 0..25 / 26..49) ----
        const int xrow = lane & 15;
        const int half = lane >> 4;
        const float* grow = tlx + (size_t)(n0w + xrow) * (TT2 * EE) + half * 26;
        const uint32_t soff = (uint32_t)(xrow * XW + half * 26) * 4u;

        // prologue: prefetch t = 0,1,2 (3 groups in flight)
#pragma unroll
        for (int s = 0; s < 3; s++) {
            int te = dir ? (TT2 - 1 - s) : s;
            uint32_t dst = wb + (uint32_t)s * XBUF_BYTES;
            const float* gp = grow + te * EE;
#pragma unroll
            for (int j = 0; j < 13; j++)
                if (half == 0 || j < 12)
                    cp_async8(dst + soff + 8u * j, gp + 2 * j);
            CP_COMMIT();
        }

        uint32_t ha[2][4];
#pragma unroll
        for (int kt = 0; kt < 2; kt++)
#pragma unroll
            for (int i = 0; i < 4; i++) ha[kt][i] = 0u;

        float accx[4][4], acch[4][4];

#pragma unroll 1
        for (int t = 0; t < TT2; t++) {
            // x(t) ready when <=2 newer groups pending
            CP_WAIT2();
            __syncwarp();

            // x contribution — 4 k-tiles from buffer t&3
            const uint32_t cur = wb + (uint32_t)(t & 3) * XBUF_BYTES;
#pragma unroll
            for (int nt = 0; nt < 4; nt++) {
                accx[nt][0] = bb[nt][0]; accx[nt][1] = bb[nt][1];
                accx[nt][2] = bb[nt][0]; accx[nt][3] = bb[nt][1];
                acch[nt][0] = 0.f; acch[nt][1] = 0.f; acch[nt][2] = 0.f; acch[nt][3] = 0.f;
            }
#pragma unroll
            for (int kt = 0; kt < 4; kt++) {
                uint32_t xa[4];
                uint32_t ba = cur + (uint32_t)(g * (XW * 4) + kt * 64 + t4 * 8);
                xa[0] = lds2h(ba);
                xa[1] = lds2h(ba + 8u * XW * 4u);
                xa[2] = lds2h(ba + 32u);
                xa[3] = lds2h(ba + 8u * XW * 4u + 32u);
#pragma unroll
                for (int nt = 0; nt < 4; nt++)
                    mma16(accx[nt], xa, wbx[kt][nt]);
            }

            // issue prefetch(t+3); empty commit in the tail keeps group count constant
            if (t + 3 < TT2) {
                int te = dir ? (TT2 - 4 - t) : (t + 3);
                uint32_t dst = wb + (uint32_t)((t + 3) & 3) * XBUF_BYTES;
                const float* gp = grow + te * EE;
#pragma unroll
                for (int j = 0; j < 13; j++)
                    if (half == 0 || j < 12)
                        cp_async8(dst + soff + 8u * j, gp + 2 * j);
            }
            CP_COMMIT();

            // h contribution (recurrence critical path; pure register chain)
#pragma unroll
            for (int kt = 0; kt < 2; kt++)
#pragma unroll
                for (int nt = 0; nt < 4; nt++)
                    mma16(acch[nt], ha[kt], wbh[kt][nt]);

            // combine + tanh
            float v[4][4];
#pragma unroll
            for (int nt = 0; nt < 4; nt++)
#pragma unroll
                for (int i = 0; i < 4; i++)
                    v[nt][i] = ftanh(accx[nt][i] + acch[nt][i]);

            if (t == TT2 - 1) {
#pragma unroll
                for (int nt = 0; nt < 4; nt++) {
                    int col = dir * 32 + nt * 8 + t4 * 2;
                    *(float2*)(g_h2 + (size_t)(n0w + g) * 64 + col)     = make_float2(v[nt][0], v[nt][1]);
                    *(float2*)(g_h2 + (size_t)(n0w + g + 8) * 64 + col) = make_float2(v[nt][2], v[nt][3]);
                }
            } else {
                // C->A fragment identity: next-step A comes from this thread's own C values.
                // ha[kt] = { (g, k-low), (g+8, k-low), (g, k-high), (g+8, k-high) }
#pragma unroll
                for (int kt = 0; kt < 2; kt++) {
                    ha[kt][0] = pack_h2(v[2 * kt][0],     v[2 * kt][1]);
                    ha[kt][1] = pack_h2(v[2 * kt][2],     v[2 * kt][3]);
                    ha[kt][2] = pack_h2(v[2 * kt + 1][0], v[2 * kt + 1][1]);
                    ha[kt][3] = pack_h2(v[2 * kt + 1][2], v[2 * kt + 1][3]);
                }
            }
        }
        return;
    }

    // ---------------- text shuffle path (blocks 1024..1279, 4 warps each) ----------------
    {
        float* s_wi = dyn;                                  // [2][HH*EE]
        float* s_wh = s_wi + 2 * HH * EE;                   // [2][HH*HH]
        float* s_b  = s_wh + 2 * HH * HH;                   // [2][HH]

        for (int k = tid; k < HH * EE; k += 128) { s_wi[k] = r1wif[k]; s_wi[HH * EE + k] = r1wib[k]; }
        for (int k = tid; k < HH * HH; k += 128) { s_wh[k] = r1whf[k]; s_wh[HH * HH + k] = r1whb[k]; }
        if (tid < HH) s_b[tid] = r1bif[tid] + r1bhf[tid];
        else if (tid < 2 * HH) { int j = tid - HH; s_b[HH + j] = r1bib[j] + r1bhb[j]; }
        __syncthreads();

        const int wglob = ((int)blockIdx.x - 1024) * 4 + wid;   // 0..1023
        const int dir = wglob & 1;
        const int seq = wglob >> 1;

        float wi[EE], wh[HH];
#pragma unroll
        for (int e = 0; e < EE; e++) wi[e] = s_wi[dir * HH * EE + lane * EE + e];
#pragma unroll
        for (int j = 0; j < HH; j++) wh[j] = s_wh[dir * HH * HH + lane * HH + j];
        const float biasv = s_b[dir * HH + lane];

        float h = 0.f;
        const float* xp = txx + (size_t)seq * TT * EE;

        const float* xt0 = xp + (size_t)(dir ? (TT - 1) : 0) * EE;
        float x1 = xt0[lane];
        float x2 = (lane < EE - 32) ? xt0[32 + lane] : 0.f;

#pragma unroll 1
        for (int t = 0; t < TT; t++) {
            float nx1 = 0.f, nx2 = 0.f;
            if (t + 1 < TT) {
                const float* xtn = xp + (size_t)(dir ? (TT - 2 - t) : (t + 1)) * EE;
                nx1 = xtn[lane];
                nx2 = (lane < EE - 32) ? xtn[32 + lane] : 0.f;
            }
            float a0 = biasv, a1 = 0.f, a2 = 0.f, a3 = 0.f;
#pragma unroll
            for (int e = 0; e < 32; e += 4) {
                a0 = fmaf(__shfl_sync(0xffffffffu, x1, e + 0), wi[e + 0], a0);
                a1 = fmaf(__shfl_sync(0xffffffffu, x1, e + 1), wi[e + 1], a1);
                a2 = fmaf(__shfl_sync(0xffffffffu, x1, e + 2), wi[e + 2], a2);
                a3 = fmaf(__shfl_sync(0xffffffffu, x1, e + 3), wi[e + 3], a3);
            }
#pragma unroll
            for (int e = 0; e < 16; e += 4) {
                a0 = fmaf(__shfl_sync(0xffffffffu, x2, e + 0), wi[32 + e + 0], a0);
                a1 = fmaf(__shfl_sync(0xffffffffu, x2, e + 1), wi[32 + e + 1], a1);
                a2 = fmaf(__shfl_sync(0xffffffffu, x2, e + 2), wi[32 + e + 2], a2);
                a3 = fmaf(__shfl_sync(0xffffffffu, x2, e + 3), wi[32 + e + 3], a3);
            }
            a0 = fmaf(__shfl_sync(0xffffffffu, x2, 16), wi[48], a0);
            a1 = fmaf(__shfl_sync(0xffffffffu, x2, 17), wi[49], a1);
#pragma unroll
            for (int j = 0; j < 32; j += 4) {
                a0 = fmaf(__shfl_sync(0xffffffffu, h, j + 0), wh[j + 0], a0);
                a1 = fmaf(__shfl_sync(0xffffffffu, h, j + 1), wh[j + 1], a1);
                a2 = fmaf(__shfl_sync(0xffffffffu, h, j + 2), wh[j + 2], a2);
                a3 = fmaf(__shfl_sync(0xffffffffu, h, j + 3), wh[j + 3], a3);
            }
            h = tanhf((a0 + a2) + (a1 + a3));
            x1 = nx1; x2 = nx2;
        }
        g_hn[(size_t)seq * 64 + dir * 32 + lane] = h;
    }
}

// ==================== fused segment stats + FC ====================
// 256 threads: 4 row-groups x 64 cols for the ragged reduce (4x MLP of the old
// version), then fc1 warp-per-output with coalesced weight reads.
__global__ __launch_bounds__(256)
void segfc_kernel(const int* __restrict__ counts,
                  const float* __restrict__ normal,
                  const float* __restrict__ fc1w, const float* __restrict__ fc1b,
                  const float* __restrict__ fc2w, const float* __restrict__ fc2b,
                  float* __restrict__ out)
{
    __shared__ float s_sum[4][64], s_min[4][64], s_max[4][64];
    __shared__ float feat[FC_IN];
    __shared__ float s_fc1[32];
    __shared__ int wsum[2];
    const int b   = blockIdx.x;
    const int tid = threadIdx.x;
    const int c   = tid & 63;
    const int grp = tid >> 6;     // 0..3
    const int lane = tid & 31;
    const int wid  = tid >> 5;    // 0..7

    // prefix: start = sum counts[0..b-1] (threads 0..63)
    if (tid < 64) {
        int part = 0;
        for (int i = tid; i < b; i += 64) part += counts[i];
#pragma unroll
        for (int o = 16; o > 0; o >>= 1) part += __shfl_xor_sync(0xffffffffu, part, o);
        if ((tid & 31) == 0) wsum[tid >> 5] = part;
    }
    __syncthreads();
    const size_t start = (size_t)(wsum[0] + wsum[1]);
    const int cnt = counts[b];

    // ragged reduce: group grp handles rows grp, grp+4, ... (2-way unrolled)
    float s = 0.f, mn = 2.f, mx = -2.f;
    {
        const float* p = g_h2 + (start) * 64 + c;
        int r = grp;
        for (; r + 4 < cnt; r += 8) {
            float v0 = p[(size_t)r * 64];
            float v1 = p[(size_t)(r + 4) * 64];
            s += v0 + v1;
            mn = fminf(mn, fminf(v0, v1));
            mx = fmaxf(mx, fmaxf(v0, v1));
        }
        for (; r < cnt; r += 4) {
            float v = p[(size_t)r * 64];
            s += v; mn = fminf(mn, v); mx = fmaxf(mx, v);
        }
    }
    s_sum[grp][c] = s; s_min[grp][c] = mn; s_max[grp][c] = mx;
    __syncthreads();

    if (tid < 64) {
        float ss = (s_sum[0][c] + s_sum[1][c]) + (s_sum[2][c] + s_sum[3][c]);
        float m0 = fminf(fminf(s_min[0][c], s_min[1][c]), fminf(s_min[2][c], s_min[3][c]));
        float m1 = fmaxf(fmaxf(s_max[0][c], s_max[1][c]), fmaxf(s_max[2][c], s_max[3][c]));
        feat[c] = g_hn[(size_t)b * 64 + c];
        feat[113 + c] = ss / (float)cnt;
        feat[177 + c] = m0;
        feat[241 + c] = m1;
    } else if (tid < 128 && tid - 64 < 49) {
        feat[64 + (tid - 64)] = normal[(size_t)b * 49 + (tid - 64)];
    }
    __syncthreads();

    // fc1: 8 warps, outputs i = wid, wid+8, ...; coalesced weight reads
    for (int i = wid; i < 32; i += 8) {
        float acc = 0.f;
        const float* w = fc1w + (size_t)i * FC_IN;
        for (int k = lane; k < FC_IN; k += 32) acc += feat[k] * w[k];
#pragma unroll
        for (int o = 16; o > 0; o >>= 1) acc += __shfl_xor_sync(0xffffffffu, acc, o);
        if (lane == 0) s_fc1[i] = tanhf(acc + fc1b[i]);
    }
    __syncthreads();

    if (wid == 0) {
        float tv = s_fc1[lane] * fc2w[lane];
#pragma unroll
        for (int o = 16; o > 0; o >>= 1) tv += __shfl_xor_sync(0xffffffffu, tv, o);
        if (lane == 0) out[b] = 1.f / (1.f + expf(-(tv + fc2b[0])));
    }
}

// ==================== launch ====================
extern "C" void kernel_launch(void* const* d_in, const int* in_sizes, int n_in,
                              void* d_out, int out_size)
{
    const float* normal   = (const float*)d_in[0];
    const float* text     = (const float*)d_in[1];
    const float* timeline = (const float*)d_in[2];

    const int* telem;
    int base;
    if (in_sizes[3] == BB) { telem = (const int*)d_in[3];  base = 4; }
    else                   { telem = (const int*)d_in[23]; base = 3; }

    const float* r1[8];
    const float* r2[8];
    for (int k = 0; k < 8; k++) r1[k] = (const float*)d_in[base + k];
    for (int k = 0; k < 8; k++) r2[k] = (const float*)d_in[base + 8 + k];
    const float* fc1w = (const float*)d_in[base + 16];
    const float* fc1b = (const float*)d_in[base + 17];
    const float* fc2w = (const float*)d_in[base + 18];
    const float* fc2b = (const float*)d_in[base + 19];
    float* out = (float*)d_out;

    // unconditional (idempotent, capture-safe): >48KB dynamic smem opt-in
    cudaFuncSetAttribute(fused_rnn, cudaFuncAttributeMaxDynamicSharedMemorySize, DYN_SMEM);

    fused_rnn<<<1280, 128, DYN_SMEM>>>(timeline, text,
        r2[0], r2[1], r2[2], r2[3], r2[4], r2[5], r2[6], r2[7],
        r1[0], r1[1], r1[2], r1[3], r1[4], r1[5], r1[6], r1[7]);

    segfc_kernel<<<BB, 256>>>(telem, normal, fc1w, fc1b, fc2w, fc2b, out);

    (void)n_in; (void)in_sizes; (void)out_size;
}

// round 10
// speedup vs baseline: 2.3863x; 2.2087x over previous
#include <cuda_runtime.h>
#include <cuda_bf16.h>
#include <cuda_fp16.h>
#include <math.h>
#include <stdint.h>

// Problem constants (fixed by setup_inputs)
#define BB 512       // batch
#define TT 64        // text seq len
#define EE 50        // embedding dim
#define HH 32        // rnn hidden
#define NN 32768     // timeline sequences
#define TT2 32       // timeline seq len
#define FC_IN 305

// ---------------- scratch (no allocations allowed) ----------------
__device__ float g_h2[(size_t)NN * 64];    // [N, 64] timeline biRNN final hidden
__device__ float g_hn[(size_t)BB * 64];    // [B, 64] text biRNN final hidden

// ==================== helpers (plain sm_100-safe: sm_80+ features only) ====================
__device__ __forceinline__ uint32_t smem_u32(const void* p) {
    uint32_t a;
    asm("{ .reg .u64 t; cvta.to.shared.u64 t, %1; cvt.u32.u64 %0, t; }" : "=r"(a) : "l"(p));
    return a;
}
__device__ __forceinline__ uint32_t pack_h2(float a, float b) {
    __half2 h = __floats2half2_rn(a, b);
    return *(uint32_t*)&h;
}
__device__ __forceinline__ uint32_t lds2h(uint32_t addr) {  // ld.shared.v2.f32 -> half2
    float x, y;
    asm volatile("ld.shared.v2.f32 {%0,%1}, [%2];" : "=f"(x), "=f"(y) : "r"(addr));
    return pack_h2(x, y);
}
__device__ __forceinline__ void sts_f(uint32_t a, float v) {
    asm volatile("st.shared.f32 [%0], %1;" :: "r"(a), "f"(v));
}
__device__ __forceinline__ void cp_async16(uint32_t saddr, const void* gaddr) {
    asm volatile("cp.async.cg.shared.global [%0], [%1], 16;" :: "r"(saddr), "l"(gaddr));
}
#define CP_COMMIT() asm volatile("cp.async.commit_group;" ::: "memory")
#define CP_WAIT1()  asm volatile("cp.async.wait_group 1;" ::: "memory")

// D += A*B : m16n8k16 fp16 in, fp32 accum (A row-major, B col-major)
__device__ __forceinline__ void mma16(float c[4], const uint32_t a[4], const uint32_t b[2]) {
    asm volatile("mma.sync.aligned.m16n8k16.row.col.f32.f16.f16.f32 "
        "{%0,%1,%2,%3}, {%4,%5,%6,%7}, {%8,%9}, {%0,%1,%2,%3};"
        : "+f"(c[0]), "+f"(c[1]), "+f"(c[2]), "+f"(c[3])
        : "r"(a[0]), "r"(a[1]), "r"(a[2]), "r"(a[3]), "r"(b[0]), "r"(b[1]));
}

// fast tanh: ex2-based exp + rcp.approx (both single-MUFU, ~1e-7 rel err)
__device__ __forceinline__ float ftanh(float x) {
    float cx = fminf(fmaxf(x, -15.f), 15.f);
    float e = __expf(2.f * cx);
    float r;
    asm("rcp.approx.f32 %0, %1;" : "=f"(r) : "f"(e + 1.f));
    return (e - 1.f) * r;
}

// ==================== per-warp SMEM (timeline branch) ====================
// Chunked packed x staging: chunk = 4 timesteps, per row 800B data (4x200)
// + 64B zero pad (k-tile-3 overread), row stride 864B. 16 rows per warp,
// 2 chunk buffers (double buffered).
#define ROWB        864
#define BUFB        (16 * ROWB)          // 13824
#define WARP_SMEM   (2 * BUFB)           // 27648
#define DYN_SMEM    (4 * WARP_SMEM)      // 110592 per CTA (needs opt-in; 2 CTAs/SM)

// coalesced chunk load: 16 rows x 800B contiguous global -> packed smem.
// 800 = 50 x 16B per row; lane l handles linear 16B-chunks l, l+32, ...
__device__ __forceinline__ void load_chunk(uint32_t dstbase, const float* __restrict__ tlx,
                                           int n0w, int base_step, int lane)
{
    const char* src0 = (const char*)tlx + (size_t)n0w * 6400 + (size_t)base_step * 200;
    int row = 0;
    int off = lane;            // 16B units within row (0..49)
#pragma unroll
    for (int i = 0; i < 25; i++) {
        cp_async16(dstbase + (uint32_t)(row * ROWB + off * 16),
                   src0 + (size_t)row * 6400 + (size_t)off * 16);
        off += 32;
        if (off >= 50) { off -= 50; row += 1; }
    }
}

// ==================== fused RNN kernel ====================
// blocks 0..1023:    timeline biRNN via mma.sync fp16-k16 (dir = b&1, 64 seqs per CTA)
// blocks 1024..1279: text biRNN via shuffle path (4 warps/block)
__global__ __launch_bounds__(128)
void fused_rnn(const float* __restrict__ tlx, const float* __restrict__ txx,
               const float* __restrict__ r2wif, const float* __restrict__ r2whf,
               const float* __restrict__ r2bif, const float* __restrict__ r2bhf,
               const float* __restrict__ r2wib, const float* __restrict__ r2whb,
               const float* __restrict__ r2bib, const float* __restrict__ r2bhb,
               const float* __restrict__ r1wif, const float* __restrict__ r1whf,
               const float* __restrict__ r1bif, const float* __restrict__ r1bhf,
               const float* __restrict__ r1wib, const float* __restrict__ r1whb,
               const float* __restrict__ r1bib, const float* __restrict__ r1bhb)
{
    extern __shared__ __align__(16) float dyn[];
    const int tid  = threadIdx.x;
    const int wid  = tid >> 5;
    const int lane = tid & 31;

    if (blockIdx.x < 1024) {
        // ---------------- timeline tensor-core path ----------------
        const int dir  = (int)(blockIdx.x & 1);
        const int tile = (int)(blockIdx.x >> 1);
        const int n0w  = tile * 64 + wid * 16;      // warp's first sequence

        const float* wih = dir ? r2wib : r2wif;
        const float* whh = dir ? r2whb : r2whf;
        const float* bi  = dir ? r2bib : r2bif;
        const float* bh  = dir ? r2bhb : r2bhf;

        const int g  = lane >> 2;    // 0..7
        const int t4 = lane & 3;     // 0..3

        const uint32_t wb = smem_u32(dyn) + (uint32_t)wid * WARP_SMEM;

        // zero the 64B pad (bytes 800..863) of all 32 rows (2 bufs x 16 rows)
        for (int i = lane; i < 2 * 16 * 16; i += 32) {
            int buf = i >> 8;
            int rem = i & 255;
            int row = rem >> 4;
            int k   = rem & 15;
            sts_f(wb + (uint32_t)(buf * BUFB + row * ROWB + 800 + k * 4), 0.f);
        }

        // ---- weight B-fragments (col-major B[k][n] = W[n][k]), fp16x2 in registers ----
        uint32_t wbh[2][4][2];   // h: K=32, 2 k-tiles
#pragma unroll
        for (int kt = 0; kt < 2; kt++)
#pragma unroll
            for (int nt = 0; nt < 4; nt++) {
                int row = nt * 8 + g;
                int c0 = kt * 16 + t4 * 2;
                wbh[kt][nt][0] = pack_h2(whh[row * 32 + c0],     whh[row * 32 + c0 + 1]);
                wbh[kt][nt][1] = pack_h2(whh[row * 32 + c0 + 8], whh[row * 32 + c0 + 9]);
            }
        uint32_t wbx[4][4][2];   // x: K=50 padded to 64, 4 k-tiles
#pragma unroll
        for (int kt = 0; kt < 4; kt++)
#pragma unroll
            for (int nt = 0; nt < 4; nt++) {
                int row = nt * 8 + g;
                int c0 = kt * 16 + t4 * 2;
                float v00 = (c0     < EE) ? wih[row * EE + c0]     : 0.f;
                float v01 = (c0 + 1 < EE) ? wih[row * EE + c0 + 1] : 0.f;
                float v10 = (c0 + 8 < EE) ? wih[row * EE + c0 + 8] : 0.f;
                float v11 = (c0 + 9 < EE) ? wih[row * EE + c0 + 9] : 0.f;
                wbx[kt][nt][0] = pack_h2(v00, v01);
                wbx[kt][nt][1] = pack_h2(v10, v11);
            }
        float bb[4][2];
#pragma unroll
        for (int nt = 0; nt < 4; nt++) {
            int col = nt * 8 + t4 * 2;
            bb[nt][0] = bi[col] + bh[col];
            bb[nt][1] = bi[col + 1] + bh[col + 1];
        }

        // prologue: load chunk 0
        {
            int bs0 = dir ? (TT2 - 4) : 0;
            load_chunk(wb, tlx, n0w, bs0, lane);
            CP_COMMIT();
        }

        uint32_t ha[2][4];
#pragma unroll
        for (int kt = 0; kt < 2; kt++)
#pragma unroll
            for (int i = 0; i < 4; i++) ha[kt][i] = 0u;

        float accx[4][4], acch[4][4];

#pragma unroll 1
        for (int c = 0; c < TT2 / 4; c++) {
            // prefetch chunk c+1 into the other buffer (empty commit in tail)
            if (c + 1 < TT2 / 4) {
                int bs = dir ? (TT2 - 8 - 4 * c) : (4 * c + 4);
                load_chunk(wb + (uint32_t)((c + 1) & 1) * BUFB, tlx, n0w, bs, lane);
            }
            CP_COMMIT();
            CP_WAIT1();          // chunk c complete (<=1 newer pending)
            __syncwarp();

            const uint32_t cb = wb + (uint32_t)(c & 1) * BUFB;

#pragma unroll
            for (int s = 0; s < 4; s++) {
                const int sidx = dir ? (3 - s) : s;    // step position within chunk
                const uint32_t sb_g  = cb + (uint32_t)(g * ROWB + sidx * 200);
                const uint32_t sb_g8 = sb_g + 8u * ROWB;

#pragma unroll
                for (int nt = 0; nt < 4; nt++) {
                    accx[nt][0] = bb[nt][0]; accx[nt][1] = bb[nt][1];
                    accx[nt][2] = bb[nt][0]; accx[nt][3] = bb[nt][1];
                    acch[nt][0] = 0.f; acch[nt][1] = 0.f; acch[nt][2] = 0.f; acch[nt][3] = 0.f;
                }
                // x contribution — 4 k-tiles (k-tile 3 overreads cols 50..63:
                // next-step data / zero pad, all finite, B=0 there -> exact 0)
#pragma unroll
                for (int kt = 0; kt < 4; kt++) {
                    uint32_t xa[4];
                    uint32_t ba = (uint32_t)(kt * 64 + t4 * 8);
                    xa[0] = lds2h(sb_g  + ba);
                    xa[1] = lds2h(sb_g8 + ba);
                    xa[2] = lds2h(sb_g  + ba + 32u);
                    xa[3] = lds2h(sb_g8 + ba + 32u);
#pragma unroll
                    for (int nt = 0; nt < 4; nt++)
                        mma16(accx[nt], xa, wbx[kt][nt]);
                }
                // h contribution (recurrence critical path; pure register chain)
#pragma unroll
                for (int kt = 0; kt < 2; kt++)
#pragma unroll
                    for (int nt = 0; nt < 4; nt++)
                        mma16(acch[nt], ha[kt], wbh[kt][nt]);

                // combine + tanh
                float v[4][4];
#pragma unroll
                for (int nt = 0; nt < 4; nt++)
#pragma unroll
                    for (int i = 0; i < 4; i++)
                        v[nt][i] = ftanh(accx[nt][i] + acch[nt][i]);

                if (c == TT2 / 4 - 1 && s == 3) {
#pragma unroll
                    for (int nt = 0; nt < 4; nt++) {
                        int col = dir * 32 + nt * 8 + t4 * 2;
                        *(float2*)(g_h2 + (size_t)(n0w + g) * 64 + col)     = make_float2(v[nt][0], v[nt][1]);
                        *(float2*)(g_h2 + (size_t)(n0w + g + 8) * 64 + col) = make_float2(v[nt][2], v[nt][3]);
                    }
                } else {
                    // C->A fragment identity: next-step A = this thread's own C values.
#pragma unroll
                    for (int kt = 0; kt < 2; kt++) {
                        ha[kt][0] = pack_h2(v[2 * kt][0],     v[2 * kt][1]);
                        ha[kt][1] = pack_h2(v[2 * kt][2],     v[2 * kt][3]);
                        ha[kt][2] = pack_h2(v[2 * kt + 1][0], v[2 * kt + 1][1]);
                        ha[kt][3] = pack_h2(v[2 * kt + 1][2], v[2 * kt + 1][3]);
                    }
                }
            }
        }
        return;
    }

    // ---------------- text shuffle path (blocks 1024..1279, 4 warps each) ----------------
    {
        float* s_wi = dyn;                                  // [2][HH*EE]
        float* s_wh = s_wi + 2 * HH * EE;                   // [2][HH*HH]
        float* s_b  = s_wh + 2 * HH * HH;                   // [2][HH]

        for (int k = tid; k < HH * EE; k += 128) { s_wi[k] = r1wif[k]; s_wi[HH * EE + k] = r1wib[k]; }
        for (int k = tid; k < HH * HH; k += 128) { s_wh[k] = r1whf[k]; s_wh[HH * HH + k] = r1whb[k]; }
        if (tid < HH) s_b[tid] = r1bif[tid] + r1bhf[tid];
        else if (tid < 2 * HH) { int j = tid - HH; s_b[HH + j] = r1bib[j] + r1bhb[j]; }
        __syncthreads();

        const int wglob = ((int)blockIdx.x - 1024) * 4 + wid;   // 0..1023
        const int dir = wglob & 1;
        const int seq = wglob >> 1;

        float wi[EE], wh[HH];
#pragma unroll
        for (int e = 0; e < EE; e++) wi[e] = s_wi[dir * HH * EE + lane * EE + e];
#pragma unroll
        for (int j = 0; j < HH; j++) wh[j] = s_wh[dir * HH * HH + lane * HH + j];
        const float biasv = s_b[dir * HH + lane];

        float h = 0.f;
        const float* xp = txx + (size_t)seq * TT * EE;

        const float* xt0 = xp + (size_t)(dir ? (TT - 1) : 0) * EE;
        float x1 = xt0[lane];
        float x2 = (lane < EE - 32) ? xt0[32 + lane] : 0.f;

#pragma unroll 1
        for (int t = 0; t < TT; t++) {
            float nx1 = 0.f, nx2 = 0.f;
            if (t + 1 < TT) {
                const float* xtn = xp + (size_t)(dir ? (TT - 2 - t) : (t + 1)) * EE;
                nx1 = xtn[lane];
                nx2 = (lane < EE - 32) ? xtn[32 + lane] : 0.f;
            }
            float a0 = biasv, a1 = 0.f, a2 = 0.f, a3 = 0.f;
#pragma unroll
            for (int e = 0; e < 32; e += 4) {
                a0 = fmaf(__shfl_sync(0xffffffffu, x1, e + 0), wi[e + 0], a0);
                a1 = fmaf(__shfl_sync(0xffffffffu, x1, e + 1), wi[e + 1], a1);
                a2 = fmaf(__shfl_sync(0xffffffffu, x1, e + 2), wi[e + 2], a2);
                a3 = fmaf(__shfl_sync(0xffffffffu, x1, e + 3), wi[e + 3], a3);
            }
#pragma unroll
            for (int e = 0; e < 16; e += 4) {
                a0 = fmaf(__shfl_sync(0xffffffffu, x2, e + 0), wi[32 + e + 0], a0);
                a1 = fmaf(__shfl_sync(0xffffffffu, x2, e + 1), wi[32 + e + 1], a1);
                a2 = fmaf(__shfl_sync(0xffffffffu, x2, e + 2), wi[32 + e + 2], a2);
                a3 = fmaf(__shfl_sync(0xffffffffu, x2, e + 3), wi[32 + e + 3], a3);
            }
            a0 = fmaf(__shfl_sync(0xffffffffu, x2, 16), wi[48], a0);
            a1 = fmaf(__shfl_sync(0xffffffffu, x2, 17), wi[49], a1);
#pragma unroll
            for (int j = 0; j < 32; j += 4) {
                a0 = fmaf(__shfl_sync(0xffffffffu, h, j + 0), wh[j + 0], a0);
                a1 = fmaf(__shfl_sync(0xffffffffu, h, j + 1), wh[j + 1], a1);
                a2 = fmaf(__shfl_sync(0xffffffffu, h, j + 2), wh[j + 2], a2);
                a3 = fmaf(__shfl_sync(0xffffffffu, h, j + 3), wh[j + 3], a3);
            }
            h = tanhf((a0 + a2) + (a1 + a3));
            x1 = nx1; x2 = nx2;
        }
        g_hn[(size_t)seq * 64 + dir * 32 + lane] = h;
    }
}

// ==================== fused segment stats + FC ====================
// 256 threads: 4 row-groups x 64 cols for the ragged reduce, then fc1
// warp-per-output with coalesced weight reads.
__global__ __launch_bounds__(256)
void segfc_kernel(const int* __restrict__ counts,
                  const float* __restrict__ normal,
                  const float* __restrict__ fc1w, const float* __restrict__ fc1b,
                  const float* __restrict__ fc2w, const float* __restrict__ fc2b,
                  float* __restrict__ out)
{
    __shared__ float s_sum[4][64], s_min[4][64], s_max[4][64];
    __shared__ float feat[FC_IN];
    __shared__ float s_fc1[32];
    __shared__ int wsum[2];
    const int b   = blockIdx.x;
    const int tid = threadIdx.x;
    const int c   = tid & 63;
    const int grp = tid >> 6;     // 0..3
    const int lane = tid & 31;
    const int wid  = tid >> 5;    // 0..7

    // prefix: start = sum counts[0..b-1] (threads 0..63)
    if (tid < 64) {
        int part = 0;
        for (int i = tid; i < b; i += 64) part += counts[i];
#pragma unroll
        for (int o = 16; o > 0; o >>= 1) part += __shfl_xor_sync(0xffffffffu, part, o);
        if ((tid & 31) == 0) wsum[tid >> 5] = part;
    }
    __syncthreads();
    const size_t start = (size_t)(wsum[0] + wsum[1]);
    const int cnt = counts[b];

    // ragged reduce: group grp handles rows grp, grp+4, ... (2-way unrolled)
    float s = 0.f, mn = 2.f, mx = -2.f;
    {
        const float* p = g_h2 + start * 64 + c;
        int r = grp;
        for (; r + 4 < cnt; r += 8) {
            float v0 = p[(size_t)r * 64];
            float v1 = p[(size_t)(r + 4) * 64];
            s += v0 + v1;
            mn = fminf(mn, fminf(v0, v1));
            mx = fmaxf(mx, fmaxf(v0, v1));
        }
        for (; r < cnt; r += 4) {
            float v = p[(size_t)r * 64];
            s += v; mn = fminf(mn, v); mx = fmaxf(mx, v);
        }
    }
    s_sum[grp][c] = s; s_min[grp][c] = mn; s_max[grp][c] = mx;
    __syncthreads();

    if (tid < 64) {
        float ss = (s_sum[0][c] + s_sum[1][c]) + (s_sum[2][c] + s_sum[3][c]);
        float m0 = fminf(fminf(s_min[0][c], s_min[1][c]), fminf(s_min[2][c], s_min[3][c]));
        float m1 = fmaxf(fmaxf(s_max[0][c], s_max[1][c]), fmaxf(s_max[2][c], s_max[3][c]));
        feat[c] = g_hn[(size_t)b * 64 + c];
        feat[113 + c] = ss / (float)cnt;
        feat[177 + c] = m0;
        feat[241 + c] = m1;
    } else if (tid < 128 && tid - 64 < 49) {
        feat[64 + (tid - 64)] = normal[(size_t)b * 49 + (tid - 64)];
    }
    __syncthreads();

    // fc1: 8 warps, outputs i = wid, wid+8, ...; coalesced weight reads
    for (int i = wid; i < 32; i += 8) {
        float acc = 0.f;
        const float* w = fc1w + (size_t)i * FC_IN;
        for (int k = lane; k < FC_IN; k += 32) acc += feat[k] * w[k];
#pragma unroll
        for (int o = 16; o > 0; o >>= 1) acc += __shfl_xor_sync(0xffffffffu, acc, o);
        if (lane == 0) s_fc1[i] = tanhf(acc + fc1b[i]);
    }
    __syncthreads();

    if (wid == 0) {
        float tv = s_fc1[lane] * fc2w[lane];
#pragma unroll
        for (int o = 16; o > 0; o >>= 1) tv += __shfl_xor_sync(0xffffffffu, tv, o);
        if (lane == 0) out[b] = 1.f / (1.f + expf(-(tv + fc2b[0])));
    }
}

// ==================== launch ====================
extern "C" void kernel_launch(void* const* d_in, const int* in_sizes, int n_in,
                              void* d_out, int out_size)
{
    const float* normal   = (const float*)d_in[0];
    const float* text     = (const float*)d_in[1];
    const float* timeline = (const float*)d_in[2];

    const int* telem;
    int base;
    if (in_sizes[3] == BB) { telem = (const int*)d_in[3];  base = 4; }
    else                   { telem = (const int*)d_in[23]; base = 3; }

    const float* r1[8];
    const float* r2[8];
    for (int k = 0; k < 8; k++) r1[k] = (const float*)d_in[base + k];
    for (int k = 0; k < 8; k++) r2[k] = (const float*)d_in[base + 8 + k];
    const float* fc1w = (const float*)d_in[base + 16];
    const float* fc1b = (const float*)d_in[base + 17];
    const float* fc2w = (const float*)d_in[base + 18];
    const float* fc2b = (const float*)d_in[base + 19];
    float* out = (float*)d_out;

    // unconditional (idempotent, capture-safe): >48KB dynamic smem opt-in
    cudaFuncSetAttribute(fused_rnn, cudaFuncAttributeMaxDynamicSharedMemorySize, DYN_SMEM);

    fused_rnn<<<1280, 128, DYN_SMEM>>>(timeline, text,
        r2[0], r2[1], r2[2], r2[3], r2[4], r2[5], r2[6], r2[7],
        r1[0], r1[1], r1[2], r1[3], r1[4], r1[5], r1[6], r1[7]);

    segfc_kernel<<<BB, 256>>>(telem, normal, fc1w, fc1b, fc2w, fc2b, out);

    (void)n_in; (void)in_sizes; (void)out_size;
}